// round 5
// baseline (speedup 1.0000x reference)
#include <cuda_runtime.h>

// MissingValueImputer — algebraically reduced.
// Key identity: h_in is broadcast over the node axis, so the GAT attention
// output is exactly relu(h0 @ gat_W^T) independent of node index and of adj.
// Remaining work: 3 small GEMMs + cosine top-k adjacency (second output).
//
// Shapes (fixed by setup_inputs): B*W=512, N=128, F=128, H=4, C=H*F=512, k=30.

#define BW 512
#define NN 128
#define FF 128
#define CC 512

// Scratch (allocation-free rule: __device__ globals).
__device__ float g_h0T[FF * BW];  // h0 transposed: [f][b]
__device__ float g_pT[CC * BW];   // relu(g) transposed: [c][b]

// ---------------------------------------------------------------------------
// K1: adjacency. One block per row i, 128 threads (one per column j).
// sim[i][j] = (e_i/|e_i|) . (e_j/|e_j|); adj[i][j] = 1 iff stable-rank(j) < k.
// Rank counting (strictly-greater, or equal with lower index) reproduces
// jax.lax.top_k semantics exactly.
// ---------------------------------------------------------------------------
__global__ void adj_kernel(const float* __restrict__ emb,
                           const int* __restrict__ kptr,
                           float* __restrict__ adj_out) {
    __shared__ float ei[FF];
    __shared__ float simrow[NN];
    __shared__ float inv_i_s;
    const int i = blockIdx.x;
    const int t = threadIdx.x;

    ei[t] = emb[i * FF + t];
    __syncthreads();

    if (t == 0) {
        float s = 0.f;
        #pragma unroll 8
        for (int f = 0; f < FF; ++f) s += ei[f] * ei[f];
        inv_i_s = 1.0f / sqrtf(s);
    }

    // |e_t| for this thread's column
    float nj = 0.f;
    #pragma unroll 4
    for (int f = 0; f < FF; ++f) {
        float v = emb[t * FF + f];
        nj += v * v;
    }
    const float invj = 1.0f / sqrtf(nj);
    __syncthreads();

    const float inv_i = inv_i_s;
    float d = 0.f;
    #pragma unroll 4
    for (int f = 0; f < FF; ++f)
        d += (ei[f] * inv_i) * (emb[t * FF + f] * invj);
    simrow[t] = d;
    __syncthreads();

    const int k = kptr ? *kptr : 30;
    const float mine = simrow[t];
    int rank = 0;
    #pragma unroll 8
    for (int j = 0; j < NN; ++j) {
        const float v = simrow[j];
        rank += (v > mine || (v == mine && j < t)) ? 1 : 0;
    }
    adj_out[i * NN + t] = (rank < k) ? 1.0f : 0.0f;
}

// ---------------------------------------------------------------------------
// K2: h0T[o][b] = x[b,:] . fp_W[:,o] + fp_b[o].
// One block per batch row b, 128 threads (one per output feature o).
// fp_W[f*FF+o] is coalesced across threads.
// ---------------------------------------------------------------------------
__global__ void h0_kernel(const float* __restrict__ x,
                          const float* __restrict__ fpW,
                          const float* __restrict__ fpb) {
    __shared__ float xs[NN];
    const int b = blockIdx.x;
    const int o = threadIdx.x;
    xs[o] = x[b * NN + o];
    __syncthreads();
    float s = fpb[o];
    #pragma unroll 4
    for (int f = 0; f < NN; ++f)
        s += xs[f] * fpW[f * FF + o];
    g_h0T[o * BW + b] = s;
}

// ---------------------------------------------------------------------------
// K3: pT[c][b] = relu( sum_f h0T[f][b] * gat_W[c][f] ),  gat_W viewed (512,128).
// Block handles 8 consecutive c (amortizes h0T reads 8x), 128 threads over b,
// each thread covers 4 b-strips. h0T reads coalesced across threads.
// ---------------------------------------------------------------------------
__global__ void gat_kernel(const float* __restrict__ gatW) {
    __shared__ float ws[8 * FF];
    const int t = threadIdx.x;
    const int c0 = blockIdx.x * 8;
    for (int i = t; i < 8 * FF; i += 128)
        ws[i] = gatW[c0 * FF + i];
    __syncthreads();

    float acc[8][4];
    #pragma unroll
    for (int cc = 0; cc < 8; ++cc)
        #pragma unroll
        for (int q = 0; q < 4; ++q) acc[cc][q] = 0.f;

    for (int f = 0; f < FF; ++f) {
        const float* row = g_h0T + f * BW + t;
        const float v0 = row[0];
        const float v1 = row[128];
        const float v2 = row[256];
        const float v3 = row[384];
        #pragma unroll
        for (int cc = 0; cc < 8; ++cc) {
            const float w = ws[cc * FF + f];
            acc[cc][0] += w * v0;
            acc[cc][1] += w * v1;
            acc[cc][2] += w * v2;
            acc[cc][3] += w * v3;
        }
    }

    #pragma unroll
    for (int cc = 0; cc < 8; ++cc) {
        float* dst = g_pT + (c0 + cc) * BW + t;
        dst[0]   = fmaxf(acc[cc][0], 0.f);
        dst[128] = fmaxf(acc[cc][1], 0.f);
        dst[256] = fmaxf(acc[cc][2], 0.f);
        dst[384] = fmaxf(acc[cc][3], 0.f);
    }
}

// ---------------------------------------------------------------------------
// K4: imp[b][n] = sum_c pT[c][b]*op_W[c][n] + op_b[n];
//     out[b][n] = x*(1-mask) + imp*mask.
// Block handles 8 batch rows (amortizes op_W reads 8x), 128 threads over n.
// op_W[c*NN+n] coalesced; pT staged in smem as ps[c][r] (broadcast reads).
// ---------------------------------------------------------------------------
__global__ void out_kernel(const float* __restrict__ x,
                           const float* __restrict__ mask,
                           const float* __restrict__ opW,
                           const float* __restrict__ opb,
                           float* __restrict__ out) {
    __shared__ float ps[CC * 8];  // [c][r]
    const int t = threadIdx.x;
    const int b0 = blockIdx.x * 8;
    for (int i = t; i < CC * 8; i += 128) {
        const int c = i >> 3;
        const int r = i & 7;
        ps[i] = g_pT[c * BW + b0 + r];
    }
    __syncthreads();

    float acc[8];
    #pragma unroll
    for (int r = 0; r < 8; ++r) acc[r] = 0.f;

    for (int c = 0; c < CC; ++c) {
        const float w = opW[c * NN + t];
        const float* p = ps + c * 8;
        #pragma unroll
        for (int r = 0; r < 8; ++r)
            acc[r] += p[r] * w;
    }

    const float bias = opb[t];
    #pragma unroll
    for (int r = 0; r < 8; ++r) {
        const int idx = (b0 + r) * NN + t;
        const float m = mask[idx];
        out[idx] = x[idx] * (1.0f - m) + (acc[r] + bias) * m;
    }
}

// ---------------------------------------------------------------------------
// Launch. Inputs (metadata order): x, mask, node_emb, gat_W, gat_a (unused),
// fp_W, fp_b, op_W, op_b, k. Output: [output(512*128) | adj(128*128)] fp32.
// ---------------------------------------------------------------------------
extern "C" void kernel_launch(void* const* d_in, const int* in_sizes, int n_in,
                              void* d_out, int out_size) {
    (void)in_sizes; (void)out_size;
    const float* x    = (const float*)d_in[0];
    const float* mask = (const float*)d_in[1];
    const float* emb  = (const float*)d_in[2];
    const float* gatW = (const float*)d_in[3];
    const float* fpW  = (const float*)d_in[5];
    const float* fpb  = (const float*)d_in[6];
    const float* opW  = (const float*)d_in[7];
    const float* opb  = (const float*)d_in[8];
    const int*   kptr = (n_in >= 10) ? (const int*)d_in[9] : nullptr;

    float* out = (float*)d_out;
    float* adj = out + BW * NN;  // second tuple element

    adj_kernel<<<NN, NN>>>(emb, kptr, adj);
    h0_kernel<<<BW, FF>>>(x, fpW, fpb);
    gat_kernel<<<CC / 8, 128>>>(gatW);
    out_kernel<<<BW / 8, 128>>>(x, mask, opW, opb, out);
}

// round 8
// speedup vs baseline: 2.3243x; 2.3243x over previous
#include <cuda_runtime.h>

// MissingValueImputer — algebraically reduced (see R2 derivation):
// broadcast over node axis makes GAT attention output exactly
// relu(h0 @ gat_W^T) independent of node index and adjacency.
// R5: kill MLP=1 latency serialization in every GEMM loop (out_kernel was
// 512 dependent LDG iterations = 64.6us). Batch loads 8-wide, float4
// everywhere, more blocks, fuse adj+h0.

#define BW 512
#define NN 128
#define FF 128
#define CC 512

__device__ float g_h0T[FF * BW];  // [f][b]
__device__ float g_pT[CC * BW];   // [c][b]

// ---------------------------------------------------------------------------
// Fused K1: blocks [0,128) = adjacency rows; blocks [128,256) = h0 (4 b-rows).
// ---------------------------------------------------------------------------
__global__ void adj_h0_kernel(const float* __restrict__ emb,
                              const int* __restrict__ kptr,
                              float* __restrict__ adj_out,
                              const float* __restrict__ x,
                              const float* __restrict__ fpW,
                              const float* __restrict__ fpb) {
    __shared__ float sm[520];
    const int t = threadIdx.x;

    if (blockIdx.x < NN) {
        // ----- adjacency row i -----
        const int i = blockIdx.x;
        float* ei = sm;            // [128]
        float* simrow = sm + 128;  // [128]
        ei[t] = emb[i * FF + t];
        __syncthreads();

        // own-row norm + dot(row_t, row_i), vectorized
        const float4* rowv = (const float4*)(emb + t * FF);
        const float4* eiv  = (const float4*)ei;
        float nj = 0.f, dot = 0.f;
        #pragma unroll
        for (int f = 0; f < FF / 4; ++f) {
            float4 r = rowv[f];
            float4 e = eiv[f];
            nj  += r.x * r.x + r.y * r.y + r.z * r.z + r.w * r.w;
            dot += e.x * r.x + e.y * r.y + e.z * r.z + e.w * r.w;
        }
        const float invj = 1.0f / sqrtf(nj);
        if (t == i) sm[512] = invj;       // row i's inverse norm
        __syncthreads();
        simrow[t] = dot * invj * sm[512];
        __syncthreads();

        const int k = kptr ? *kptr : 30;
        const float mine = simrow[t];
        int rank = 0;
        #pragma unroll 16
        for (int j = 0; j < NN; ++j) {
            const float v = simrow[j];
            rank += (v > mine || (v == mine && j < t)) ? 1 : 0;
        }
        adj_out[i * NN + t] = (rank < k) ? 1.0f : 0.0f;
    } else {
        // ----- h0 for 4 batch rows -----
        const int b0 = (blockIdx.x - NN) * 4;
        float* xs = sm;  // [4][128]
        #pragma unroll
        for (int r = 0; r < 4; ++r)
            xs[r * FF + t] = x[(b0 + r) * NN + t];
        __syncthreads();

        const float bias = fpb[t];
        float acc0 = bias, acc1 = bias, acc2 = bias, acc3 = bias;
        for (int f = 0; f < FF; f += 4) {
            // 4 independent coalesced LDGs in flight
            const float w0 = fpW[(f + 0) * FF + t];
            const float w1 = fpW[(f + 1) * FF + t];
            const float w2 = fpW[(f + 2) * FF + t];
            const float w3 = fpW[(f + 3) * FF + t];
            float4 x0 = *(const float4*)&xs[0 * FF + f];
            float4 x1 = *(const float4*)&xs[1 * FF + f];
            float4 x2 = *(const float4*)&xs[2 * FF + f];
            float4 x3 = *(const float4*)&xs[3 * FF + f];
            acc0 += x0.x * w0 + x0.y * w1 + x0.z * w2 + x0.w * w3;
            acc1 += x1.x * w0 + x1.y * w1 + x1.z * w2 + x1.w * w3;
            acc2 += x2.x * w0 + x2.y * w1 + x2.z * w2 + x2.w * w3;
            acc3 += x3.x * w0 + x3.y * w1 + x3.z * w2 + x3.w * w3;
        }
        // b0 is 4-aligned -> vector store of 4 consecutive b
        *(float4*)&g_h0T[t * BW + b0] = make_float4(acc0, acc1, acc2, acc3);
    }
}

// ---------------------------------------------------------------------------
// K2: pT[c][b] = relu(sum_f h0T[f][b] * gat_W[c][f]).
// grid (64 c-groups of 8, 2 b-halves of 256), 128 threads.
// f unrolled x4: 8 independent LDGs per group; float4 LDS on weights.
// ---------------------------------------------------------------------------
__global__ void gat_kernel(const float* __restrict__ gatW) {
    __shared__ float ws[8 * FF];
    const int t = threadIdx.x;
    const int c0 = blockIdx.x * 8;
    const int bb = blockIdx.y * 256;

    for (int i = t; i < 8 * FF; i += 128)
        ws[i] = gatW[c0 * FF + i];
    __syncthreads();

    float acc[8][2];
    #pragma unroll
    for (int cc = 0; cc < 8; ++cc) { acc[cc][0] = 0.f; acc[cc][1] = 0.f; }

    for (int f = 0; f < FF; f += 4) {
        float v[4][2];
        #pragma unroll
        for (int u = 0; u < 4; ++u) {
            v[u][0] = g_h0T[(f + u) * BW + bb + t];
            v[u][1] = g_h0T[(f + u) * BW + bb + 128 + t];
        }
        #pragma unroll
        for (int cc = 0; cc < 8; ++cc) {
            const float4 wv = *(const float4*)&ws[cc * FF + f];
            acc[cc][0] += wv.x * v[0][0] + wv.y * v[1][0] + wv.z * v[2][0] + wv.w * v[3][0];
            acc[cc][1] += wv.x * v[0][1] + wv.y * v[1][1] + wv.z * v[2][1] + wv.w * v[3][1];
        }
    }

    #pragma unroll
    for (int cc = 0; cc < 8; ++cc) {
        float* dst = g_pT + (c0 + cc) * BW + bb + t;
        dst[0]   = fmaxf(acc[cc][0], 0.f);
        dst[128] = fmaxf(acc[cc][1], 0.f);
    }
}

// ---------------------------------------------------------------------------
// K3: imp[b][n] = sum_c pT[c][b]*op_W[c][n] + op_b[n]; blend with mask.
// grid 128 (4 rows/block), 256 threads = 128 n x 2 c-halves.
// 8 independent LDGs per c-chunk; float4 LDS on staged p; smem reduce halves.
// ---------------------------------------------------------------------------
__global__ void out_kernel(const float* __restrict__ x,
                           const float* __restrict__ mask,
                           const float* __restrict__ opW,
                           const float* __restrict__ opb,
                           float* __restrict__ out) {
    __shared__ float ps[4 * CC];   // [r][c]
    __shared__ float red[4 * NN];  // upper-half partials
    const int t = threadIdx.x;
    const int n = t & 127;
    const int h = t >> 7;
    const int b0 = blockIdx.x * 4;

    for (int i = t; i < 4 * CC; i += 256) {
        const int c = i >> 2;
        const int r = i & 3;
        ps[r * CC + c] = g_pT[c * BW + b0 + r];
    }
    __syncthreads();

    float acc[4] = {0.f, 0.f, 0.f, 0.f};
    const int cb = h * 256;
    for (int cc = 0; cc < 256; cc += 8) {
        float w[8];
        #pragma unroll
        for (int j = 0; j < 8; ++j)
            w[j] = opW[(cb + cc + j) * NN + n];   // 8 LDGs in flight, coalesced
        #pragma unroll
        for (int r = 0; r < 4; ++r) {
            const float4 p0 = *(const float4*)&ps[r * CC + cb + cc];
            const float4 p1 = *(const float4*)&ps[r * CC + cb + cc + 4];
            acc[r] += p0.x * w[0] + p0.y * w[1] + p0.z * w[2] + p0.w * w[3]
                    + p1.x * w[4] + p1.y * w[5] + p1.z * w[6] + p1.w * w[7];
        }
    }

    if (h) {
        #pragma unroll
        for (int r = 0; r < 4; ++r) red[r * NN + n] = acc[r];
    }
    __syncthreads();
    if (!h) {
        const float bias = opb[n];
        #pragma unroll
        for (int r = 0; r < 4; ++r) {
            const float imp = acc[r] + red[r * NN + n] + bias;
            const int idx = (b0 + r) * NN + n;
            const float m = mask[idx];
            out[idx] = x[idx] * (1.0f - m) + imp * m;
        }
    }
}

// ---------------------------------------------------------------------------
extern "C" void kernel_launch(void* const* d_in, const int* in_sizes, int n_in,
                              void* d_out, int out_size) {
    (void)in_sizes; (void)out_size;
    const float* x    = (const float*)d_in[0];
    const float* mask = (const float*)d_in[1];
    const float* emb  = (const float*)d_in[2];
    const float* gatW = (const float*)d_in[3];
    const float* fpW  = (const float*)d_in[5];
    const float* fpb  = (const float*)d_in[6];
    const float* opW  = (const float*)d_in[7];
    const float* opb  = (const float*)d_in[8];
    const int*   kptr = (n_in >= 10) ? (const int*)d_in[9] : nullptr;

    float* out = (float*)d_out;
    float* adj = out + BW * NN;

    adj_h0_kernel<<<NN + BW / 4, 128>>>(emb, kptr, adj, x, fpW, fpb);
    gat_kernel<<<dim3(CC / 8, 2), 128>>>(gatW);
    out_kernel<<<BW / 4, 256>>>(x, mask, opW, opb, out);
}

// round 9
// speedup vs baseline: 3.0840x; 1.3268x over previous
#include <cuda_runtime.h>

// MissingValueImputer — algebraically reduced (R2 derivation): GAT output is
// exactly relu(h0 @ gat_W^T), independent of node index and adjacency.
// R8: single persistent kernel (128 blocks x 256 thr, all co-resident) with
// software grid barriers — removes inter-kernel launch/drain gaps that
// dominated the 3-kernel version (chip was >90% idle).

#define BW 512
#define NN 128
#define FF 128
#define CC 512
#define GRID 128
#define TPB 256

__device__ float g_h0T[FF * BW];  // [f][b]
__device__ float g_pT[CC * BW];   // [c][b]
__device__ unsigned g_c1 = 0, g_c2 = 0, g_done = 0;

// Grid barrier: count up, spin until GRID. Counters are restored to 0 by the
// reset protocol (g_c1 reset by last arriver at barrier 2, g_c2/g_done at
// kernel end), so every launch/replay starts from a clean state.
__device__ __forceinline__ void gbar(unsigned* cnt, unsigned* reset_prev) {
    __syncthreads();
    if (threadIdx.x == 0) {
        __threadfence();                      // release this block's writes
        unsigned prev = atomicAdd(cnt, 1u);
        if (prev == GRID - 1u && reset_prev)  // all blocks passed prev barrier
            *reset_prev = 0u;
        while (*(volatile unsigned*)cnt < GRID) {}
        __threadfence();                      // acquire other blocks' writes
    }
    __syncthreads();
}

__global__ __launch_bounds__(TPB, 1)
void fused_kernel(const float* __restrict__ x, const float* __restrict__ mask,
                  const float* __restrict__ emb, const float* __restrict__ gatW,
                  const float* __restrict__ fpW, const float* __restrict__ fpb,
                  const float* __restrict__ opW, const float* __restrict__ opb,
                  const int* __restrict__ kptr,
                  float* __restrict__ out, float* __restrict__ adj_out) {
    __shared__ float sm[2560];
    const int t = threadIdx.x;
    const int blk = blockIdx.x;

    // ================= Phase A: adjacency (half 1) + h0 (half 2) ==========
    if (t < 128) {
        // ----- adjacency row i = blk -----
        float* ei = sm;            // [128]
        float* simrow = sm + 128;  // [128]
        ei[t] = emb[blk * FF + t];
        asm volatile("bar.sync 1, 128;" ::: "memory");

        const float4* rowv = (const float4*)(emb + t * FF);
        const float4* eiv  = (const float4*)ei;
        float nj = 0.f, dot = 0.f;
        #pragma unroll
        for (int f = 0; f < FF / 4; ++f) {
            float4 r = rowv[f];
            float4 e = eiv[f];
            nj  += r.x * r.x + r.y * r.y + r.z * r.z + r.w * r.w;
            dot += e.x * r.x + e.y * r.y + e.z * r.z + e.w * r.w;
        }
        const float invj = 1.0f / sqrtf(nj);
        if (t == blk) sm[256] = invj;   // row i's inverse norm
        asm volatile("bar.sync 1, 128;" ::: "memory");
        simrow[t] = dot * invj * sm[256];
        asm volatile("bar.sync 1, 128;" ::: "memory");

        const int k = kptr ? *kptr : 30;
        const float mine = simrow[t];
        int rank = 0;
        #pragma unroll 16
        for (int j = 0; j < NN; ++j) {
            const float v = simrow[j];
            rank += (v > mine || (v == mine && j < t)) ? 1 : 0;
        }
        adj_out[blk * NN + t] = (rank < k) ? 1.0f : 0.0f;
    } else {
        // ----- h0 for 4 batch rows, b0 = blk*4 -----
        const int tt = t - 128;
        const int b0 = blk * 4;
        float* xs = sm + 512;  // [4][128]
        #pragma unroll
        for (int r = 0; r < 4; ++r)
            xs[r * FF + tt] = x[(b0 + r) * NN + tt];
        asm volatile("bar.sync 2, 128;" ::: "memory");

        const float bias = fpb[tt];
        float a0 = bias, a1 = bias, a2 = bias, a3 = bias;
        #pragma unroll 4
        for (int f = 0; f < FF; f += 4) {
            const float w0 = fpW[(f + 0) * FF + tt];
            const float w1 = fpW[(f + 1) * FF + tt];
            const float w2 = fpW[(f + 2) * FF + tt];
            const float w3 = fpW[(f + 3) * FF + tt];
            const float4 x0 = *(const float4*)&xs[0 * FF + f];
            const float4 x1 = *(const float4*)&xs[1 * FF + f];
            const float4 x2 = *(const float4*)&xs[2 * FF + f];
            const float4 x3 = *(const float4*)&xs[3 * FF + f];
            a0 += x0.x * w0 + x0.y * w1 + x0.z * w2 + x0.w * w3;
            a1 += x1.x * w0 + x1.y * w1 + x1.z * w2 + x1.w * w3;
            a2 += x2.x * w0 + x2.y * w1 + x2.z * w2 + x2.w * w3;
            a3 += x3.x * w0 + x3.y * w1 + x3.z * w2 + x3.w * w3;
        }
        *(float4*)&g_h0T[tt * BW + b0] = make_float4(a0, a1, a2, a3);
    }

    gbar(&g_c1, 0);

    // ================= Phase B: pT = relu(h0T^T gatW^T), transposed ========
    {
        const int c0 = (blk >> 1) * 8;       // 64 groups of 8 c
        const int bb = (blk & 1) * 256;      // 2 halves of 256 b
        float* ws = sm;                      // [8][128]
        for (int i = t; i < 8 * FF; i += TPB)
            ws[i] = gatW[c0 * FF + i];
        __syncthreads();

        float acc[8] = {0.f, 0.f, 0.f, 0.f, 0.f, 0.f, 0.f, 0.f};
        #pragma unroll 2
        for (int f = 0; f < FF; f += 4) {
            const float v0 = g_h0T[(f + 0) * BW + bb + t];
            const float v1 = g_h0T[(f + 1) * BW + bb + t];
            const float v2 = g_h0T[(f + 2) * BW + bb + t];
            const float v3 = g_h0T[(f + 3) * BW + bb + t];
            #pragma unroll
            for (int cc = 0; cc < 8; ++cc) {
                const float4 wv = *(const float4*)&ws[cc * FF + f];
                acc[cc] += wv.x * v0 + wv.y * v1 + wv.z * v2 + wv.w * v3;
            }
        }
        #pragma unroll
        for (int cc = 0; cc < 8; ++cc)
            g_pT[(c0 + cc) * BW + bb + t] = fmaxf(acc[cc], 0.f);
    }

    gbar(&g_c2, &g_c1);   // also resets g_c1 for the next launch

    // ================= Phase C: out = blend(x, pT^T @ opW + opb) ===========
    {
        const int n = t & 127;
        const int h = t >> 7;
        const int b0 = blk * 4;
        float* ps  = sm;         // [4][512]
        float* red = sm + 2048;  // [4][128]

        for (int i = t; i < 4 * CC; i += TPB) {
            const int c = i >> 2;
            const int r = i & 3;
            ps[r * CC + c] = g_pT[c * BW + b0 + r];
        }
        __syncthreads();

        float acc[4] = {0.f, 0.f, 0.f, 0.f};
        const int cb = h * 256;
        for (int cc = 0; cc < 256; cc += 8) {
            float w[8];
            #pragma unroll
            for (int j = 0; j < 8; ++j)
                w[j] = opW[(cb + cc + j) * NN + n];   // 8 LDGs in flight
            #pragma unroll
            for (int r = 0; r < 4; ++r) {
                const float4 p0 = *(const float4*)&ps[r * CC + cb + cc];
                const float4 p1 = *(const float4*)&ps[r * CC + cb + cc + 4];
                acc[r] += p0.x * w[0] + p0.y * w[1] + p0.z * w[2] + p0.w * w[3]
                        + p1.x * w[4] + p1.y * w[5] + p1.z * w[6] + p1.w * w[7];
            }
        }

        if (h) {
            #pragma unroll
            for (int r = 0; r < 4; ++r) red[r * NN + n] = acc[r];
        }
        __syncthreads();
        if (!h) {
            const float bias = opb[n];
            #pragma unroll
            for (int r = 0; r < 4; ++r) {
                const float imp = acc[r] + red[r * NN + n] + bias;
                const int idx = (b0 + r) * NN + n;
                const float m = mask[idx];
                out[idx] = x[idx] * (1.0f - m) + imp * m;
            }
        }
    }

    // ================= Epilogue: restore counters for next launch ==========
    __syncthreads();
    if (t == 0) {
        if (atomicAdd(&g_done, 1u) == GRID - 1u) {
            g_c2 = 0u;
            g_done = 0u;
        }
    }
}

// ---------------------------------------------------------------------------
extern "C" void kernel_launch(void* const* d_in, const int* in_sizes, int n_in,
                              void* d_out, int out_size) {
    (void)in_sizes; (void)out_size;
    const float* x    = (const float*)d_in[0];
    const float* mask = (const float*)d_in[1];
    const float* emb  = (const float*)d_in[2];
    const float* gatW = (const float*)d_in[3];
    const float* fpW  = (const float*)d_in[5];
    const float* fpb  = (const float*)d_in[6];
    const float* opW  = (const float*)d_in[7];
    const float* opb  = (const float*)d_in[8];
    const int*   kptr = (n_in >= 10) ? (const int*)d_in[9] : nullptr;

    float* out = (float*)d_out;
    float* adj = out + BW * NN;

    fused_kernel<<<GRID, TPB>>>(x, mask, emb, gatW, fpW, fpb, opW, opb,
                                kptr, out, adj);
}

// round 11
// speedup vs baseline: 3.5537x; 1.1523x over previous
#include <cuda_runtime.h>

// MissingValueImputer — algebraically reduced (R2): GAT output is exactly
// relu(h0 @ gat_W^T), independent of node index and adjacency.
// R11 (= R9 resubmit; R10 was an infra failure, kernel never ran):
// ZERO grid barriers. h0 -> p -> imp -> blend is independent per batch
// row, so each block owns 4 rows end-to-end (gatW/opW streamed from L2,
// gatW staged via padded smem tiles). Adjacency = 128 extra indep blocks.

#define BW 512
#define NN 128
#define FF 128
#define CC 512
#define TPB 256

// smem pool layout (floats):
//   [0, 8448)      phase workspace: ws tile [64][132] / xs+red / red3
//   [8448, 8976)   h0s [4][132] (padded, conflict-free)
//   [8976, 11024)  ps  [4][512]
#define SM_H0S 8448
#define SM_PS  8976
#define SM_TOT 11024

__global__ __launch_bounds__(TPB, 2)
void fused_kernel(const float* __restrict__ x, const float* __restrict__ mask,
                  const float* __restrict__ emb, const float* __restrict__ gatW,
                  const float* __restrict__ fpW, const float* __restrict__ fpb,
                  const float* __restrict__ opW, const float* __restrict__ opb,
                  const int* __restrict__ kptr,
                  float* __restrict__ out, float* __restrict__ adj_out) {
    __shared__ float sm[SM_TOT];
    const int t = threadIdx.x;

    // ====================== adjacency blocks [128, 256) ====================
    if (blockIdx.x >= 128) {
        const int i = blockIdx.x - 128;
        float* ei = sm;            // [128]
        float* simrow = sm + 128;  // [128]
        float dot = 0.f, invj = 0.f;

        if (t < 128) ei[t] = emb[i * FF + t];
        __syncthreads();

        if (t < 128) {
            const float4* rowv = (const float4*)(emb + t * FF);
            const float4* eiv  = (const float4*)ei;
            float nj = 0.f;
            #pragma unroll
            for (int f = 0; f < FF / 4; ++f) {
                float4 r = rowv[f];
                float4 e = eiv[f];
                nj  += r.x * r.x + r.y * r.y + r.z * r.z + r.w * r.w;
                dot += e.x * r.x + e.y * r.y + e.z * r.z + e.w * r.w;
            }
            invj = 1.0f / sqrtf(nj);
            if (t == i) sm[256] = invj;   // row i's inverse norm
        }
        __syncthreads();
        if (t < 128) simrow[t] = dot * invj * sm[256];
        __syncthreads();

        if (t < 128) {
            const int k = kptr ? *kptr : 30;
            const float mine = simrow[t];
            int rank = 0;
            #pragma unroll 16
            for (int j = 0; j < NN; ++j) {
                const float v = simrow[j];
                rank += (v > mine || (v == mine && j < t)) ? 1 : 0;
            }
            adj_out[i * NN + t] = (rank < k) ? 1.0f : 0.0f;
        }
        return;
    }

    // ====================== compute blocks: 4 b-rows each ==================
    const int b0 = blockIdx.x * 4;
    float* h0s = sm + SM_H0S;  // [4][132] padded
    float* ps  = sm + SM_PS;   // [4][512]

    // ---- Phase 1: h0[r][o] = fp_b[o] + sum_f x[r][f] * fpW[f][o] ----------
    {
        float* xs  = sm;        // [4][128]
        float* red = sm + 512;  // [2][512]  (half-partials)
        for (int i = t; i < 512; i += TPB) xs[i] = x[b0 * NN + i];
        __syncthreads();

        const int o = t & 127, h = t >> 7;
        const int f0 = h * 64;
        float a0 = 0.f, a1 = 0.f, a2 = 0.f, a3 = 0.f;
        #pragma unroll 4
        for (int f = f0; f < f0 + 64; f += 4) {
            const float w0 = fpW[(f + 0) * FF + o];
            const float w1 = fpW[(f + 1) * FF + o];
            const float w2 = fpW[(f + 2) * FF + o];
            const float w3 = fpW[(f + 3) * FF + o];
            const float4 x0 = *(const float4*)&xs[0 * FF + f];
            const float4 x1 = *(const float4*)&xs[1 * FF + f];
            const float4 x2 = *(const float4*)&xs[2 * FF + f];
            const float4 x3 = *(const float4*)&xs[3 * FF + f];
            a0 += x0.x * w0 + x0.y * w1 + x0.z * w2 + x0.w * w3;
            a1 += x1.x * w0 + x1.y * w1 + x1.z * w2 + x1.w * w3;
            a2 += x2.x * w0 + x2.y * w1 + x2.z * w2 + x2.w * w3;
            a3 += x3.x * w0 + x3.y * w1 + x3.z * w2 + x3.w * w3;
        }
        red[h * 512 + 0 * NN + o] = a0;
        red[h * 512 + 1 * NN + o] = a1;
        red[h * 512 + 2 * NN + o] = a2;
        red[h * 512 + 3 * NN + o] = a3;
        __syncthreads();
        for (int i = t; i < 512; i += TPB) {
            const int r = i >> 7, oo = i & 127;
            h0s[r * 132 + oo] = red[i] + red[512 + i] + fpb[oo];
        }
        __syncthreads();
    }

    // ---- Phase 2: p[r][c] = relu(sum_f h0[r][f] * gatW[c][f]) -------------
    // 8 tiles of 64 c; tile staged in padded smem (stride 132 -> no bank
    // conflicts: lane c spreads banks by 4, same-c lanes broadcast; 132 f
    // = 528 B row stride keeps float4 16 B alignment).
    {
        float* ws = sm;  // [64][132]
        const int cl = t >> 2, r = t & 3;
        for (int ct = 0; ct < 8; ++ct) {
            const float* src = gatW + ct * 64 * FF;
            for (int i = t; i < 2048; i += TPB) {
                const int cc = i >> 5, f4 = (i & 31) * 4;
                *(float4*)&ws[cc * 132 + f4] = *(const float4*)&src[cc * FF + f4];
            }
            __syncthreads();

            float acc = 0.f;
            #pragma unroll
            for (int f = 0; f < FF; f += 4) {
                const float4 wv = *(const float4*)&ws[cl * 132 + f];
                const float4 hv = *(const float4*)&h0s[r * 132 + f];
                acc += wv.x * hv.x + wv.y * hv.y + wv.z * hv.z + wv.w * hv.w;
            }
            ps[r * CC + ct * 64 + cl] = fmaxf(acc, 0.f);
            __syncthreads();
        }
    }

    // ---- Phase 3: imp[r][n] = sum_c p[r][c]*opW[c][n] + opb[n]; blend -----
    {
        float* red = sm;  // [4][128] upper-half partials
        const int n = t & 127, h = t >> 7;
        const int cb = h * 256;
        float acc[4] = {0.f, 0.f, 0.f, 0.f};

        for (int cc = 0; cc < 256; cc += 8) {
            float w[8];
            #pragma unroll
            for (int j = 0; j < 8; ++j)
                w[j] = opW[(cb + cc + j) * NN + n];   // 8 LDGs in flight
            #pragma unroll
            for (int r = 0; r < 4; ++r) {
                const float4 p0 = *(const float4*)&ps[r * CC + cb + cc];
                const float4 p1 = *(const float4*)&ps[r * CC + cb + cc + 4];
                acc[r] += p0.x * w[0] + p0.y * w[1] + p0.z * w[2] + p0.w * w[3]
                        + p1.x * w[4] + p1.y * w[5] + p1.z * w[6] + p1.w * w[7];
            }
        }

        if (h) {
            #pragma unroll
            for (int r = 0; r < 4; ++r) red[r * NN + n] = acc[r];
        }
        __syncthreads();
        if (!h) {
            const float bias = opb[n];
            #pragma unroll
            for (int r = 0; r < 4; ++r) {
                const float imp = acc[r] + red[r * NN + n] + bias;
                const int idx = (b0 + r) * NN + n;
                const float m = mask[idx];
                out[idx] = x[idx] * (1.0f - m) + imp * m;
            }
        }
    }
}

// ---------------------------------------------------------------------------
extern "C" void kernel_launch(void* const* d_in, const int* in_sizes, int n_in,
                              void* d_out, int out_size) {
    (void)in_sizes; (void)out_size;
    const float* x    = (const float*)d_in[0];
    const float* mask = (const float*)d_in[1];
    const float* emb  = (const float*)d_in[2];
    const float* gatW = (const float*)d_in[3];
    const float* fpW  = (const float*)d_in[5];
    const float* fpb  = (const float*)d_in[6];
    const float* opW  = (const float*)d_in[7];
    const float* opb  = (const float*)d_in[8];
    const int*   kptr = (n_in >= 10) ? (const int*)d_in[9] : nullptr;

    float* out = (float*)d_out;
    float* adj = out + BW * NN;

    fused_kernel<<<256, TPB>>>(x, mask, emb, gatW, fpW, fpb, opW, opb,
                               kptr, out, adj);
}

// round 12
// speedup vs baseline: 4.1460x; 1.1667x over previous
#include <cuda_runtime.h>

// MissingValueImputer — algebraically reduced (R2): GAT output is exactly
// relu(h0 @ gat_W^T), independent of node index and adjacency.
// R12: 128 blocks x 512 threads. Adjacency runs warp-specialized inside
// phase 1. Phase 2 tiles 128c x 64f with register-double-buffered staging
// (next tile's LDGs fly through the barrier). Phase 3 quarter-split over c.

#define BW 512
#define NN 128
#define FF 128
#define CC 512
#define TPB 512
#define GRID 128

// smem pool (floats):
//   ws   [0, 8704)        128 x 68 (padded) weight tile   (phase 2)
//   ph1  [0, 1536)        xs[512] + red[1024]             (phase 1 h0)
//   adj  [1600, 1857)     ei[128] + simrow[128] + inv     (phase 1 adj)
//   red3 [0, 2048)        quarter partials                (phase 3)
//   h0s  [8704, 9232)     4 x 132 padded
//   ps   [9232, 11280)    4 x 512
#define SM_H0S 8704
#define SM_PS  9232
#define SM_TOT 11280

__global__ __launch_bounds__(TPB, 1)
void fused_kernel(const float* __restrict__ x, const float* __restrict__ mask,
                  const float* __restrict__ emb, const float* __restrict__ gatW,
                  const float* __restrict__ fpW, const float* __restrict__ fpb,
                  const float* __restrict__ opW, const float* __restrict__ opb,
                  const int* __restrict__ kptr,
                  float* __restrict__ out, float* __restrict__ adj_out) {
    __shared__ float sm[SM_TOT];
    const int t = threadIdx.x;
    const int blk = blockIdx.x;
    const int b0 = blk * 4;
    float* h0s = sm + SM_H0S;  // [4][132]
    float* ps  = sm + SM_PS;   // [4][512]

    // ============ Phase 1 (warp-specialized): h0 (t<256) + adjacency =======
    if (t < 256) {
        // ----- h0[r][o] for rows b0..b0+3 -----
        float* xs  = sm;        // [4][128]
        float* red = sm + 512;  // [2][512]
        for (int i = t; i < 512; i += 256) xs[i] = x[b0 * NN + i];
        asm volatile("bar.sync 3, 256;" ::: "memory");

        const int o = t & 127, h = t >> 7;
        const int f0 = h * 64;
        float a0 = 0.f, a1 = 0.f, a2 = 0.f, a3 = 0.f;
        #pragma unroll 4
        for (int f = f0; f < f0 + 64; f += 4) {
            const float w0 = fpW[(f + 0) * FF + o];
            const float w1 = fpW[(f + 1) * FF + o];
            const float w2 = fpW[(f + 2) * FF + o];
            const float w3 = fpW[(f + 3) * FF + o];
            const float4 x0 = *(const float4*)&xs[0 * FF + f];
            const float4 x1 = *(const float4*)&xs[1 * FF + f];
            const float4 x2 = *(const float4*)&xs[2 * FF + f];
            const float4 x3 = *(const float4*)&xs[3 * FF + f];
            a0 += x0.x * w0 + x0.y * w1 + x0.z * w2 + x0.w * w3;
            a1 += x1.x * w0 + x1.y * w1 + x1.z * w2 + x1.w * w3;
            a2 += x2.x * w0 + x2.y * w1 + x2.z * w2 + x2.w * w3;
            a3 += x3.x * w0 + x3.y * w1 + x3.z * w2 + x3.w * w3;
        }
        red[h * 512 + 0 * NN + o] = a0;
        red[h * 512 + 1 * NN + o] = a1;
        red[h * 512 + 2 * NN + o] = a2;
        red[h * 512 + 3 * NN + o] = a3;
        asm volatile("bar.sync 3, 256;" ::: "memory");
        for (int i = t; i < 512; i += 256) {
            const int r = i >> 7, oo = i & 127;
            h0s[r * 132 + oo] = red[i] + red[512 + i] + fpb[oo];
        }
    } else if (t < 384) {
        // ----- adjacency row i = blk (threads 256..383) -----
        const int t2 = t - 256;
        float* ei = sm + 1600;      // [128]
        float* simrow = sm + 1728;  // [128]
        ei[t2] = emb[blk * FF + t2];
        asm volatile("bar.sync 4, 128;" ::: "memory");

        const float4* rowv = (const float4*)(emb + t2 * FF);
        const float4* eiv  = (const float4*)ei;
        float nj = 0.f, dot = 0.f;
        #pragma unroll
        for (int f = 0; f < FF / 4; ++f) {
            float4 rr = rowv[f];
            float4 ee = eiv[f];
            nj  += rr.x * rr.x + rr.y * rr.y + rr.z * rr.z + rr.w * rr.w;
            dot += ee.x * rr.x + ee.y * rr.y + ee.z * rr.z + ee.w * rr.w;
        }
        const float invj = 1.0f / sqrtf(nj);
        if (t2 == blk) sm[1856] = invj;
        asm volatile("bar.sync 4, 128;" ::: "memory");
        simrow[t2] = dot * invj * sm[1856];
        asm volatile("bar.sync 4, 128;" ::: "memory");

        const int k = kptr ? *kptr : 30;
        const float mine = simrow[t2];
        int rank = 0;
        #pragma unroll 16
        for (int j = 0; j < NN; ++j) {
            const float v = simrow[j];
            rank += (v > mine || (v == mine && j < t2)) ? 1 : 0;
        }
        adj_out[blk * NN + t2] = (rank < k) ? 1.0f : 0.0f;
    }
    __syncthreads();

    // ============ Phase 2: p[r][c] = relu(sum_f h0[r][f] * gatW[c][f]) =====
    // 4 c-tiles of 128, each in 2 f-half rounds (64 f staged per round).
    // Register double-buffer: next round's LDGs issued before the barrier.
    {
        float* ws = sm;  // [128][68] padded (68*4 = 272 B, 16 B aligned)
        const int cl = t >> 2;   // c within tile
        const int r  = t & 3;
        const int srow = t >> 4;        // staging: 32 rows of 128, 16 thr/row
        const int sf4  = (t & 15) * 4;  // float4 offset within 64-f half

        float4 rg[4], rg2[4];
        // prologue: round 0 (ct=0, fh=0)
        #pragma unroll
        for (int j = 0; j < 4; ++j)
            rg[j] = *(const float4*)&gatW[(srow + j * 32) * FF + sf4];

        float acc = 0.f;
        #pragma unroll
        for (int round = 0; round < 8; ++round) {
            const int ct = round >> 1, fh = round & 1;
            // store current tile
            #pragma unroll
            for (int j = 0; j < 4; ++j)
                *(float4*)&ws[(srow + j * 32) * 68 + sf4] = rg[j];
            // prefetch next tile (flies through the barrier)
            if (round < 7) {
                const int nct = (round + 1) >> 1, nfh = (round + 1) & 1;
                #pragma unroll
                for (int j = 0; j < 4; ++j)
                    rg2[j] = *(const float4*)
                        &gatW[(nct * 128 + srow + j * 32) * FF + nfh * 64 + sf4];
            }
            __syncthreads();

            if (fh == 0) acc = 0.f;
            const float* wrow = &ws[cl * 68];
            const float* hrow = &h0s[r * 132 + fh * 64];
            #pragma unroll
            for (int f = 0; f < 64; f += 4) {
                const float4 wv = *(const float4*)&wrow[f];
                const float4 hv = *(const float4*)&hrow[f];
                acc += wv.x * hv.x + wv.y * hv.y + wv.z * hv.z + wv.w * hv.w;
            }
            if (fh == 1) ps[r * CC + ct * 128 + cl] = fmaxf(acc, 0.f);
            __syncthreads();
            #pragma unroll
            for (int j = 0; j < 4; ++j) rg[j] = rg2[j];
        }
    }

    // ============ Phase 3: imp = p @ opW + opb; blend ======================
    // 512 threads = 128 n x 4 c-quarters of 128; smem-reduce quarters.
    {
        float* red = sm;  // [4 q][4 r][128 n] = 2048
        const int n = t & 127;
        const int q = t >> 7;
        const int cb = q * 128;
        float acc[4] = {0.f, 0.f, 0.f, 0.f};

        for (int cc = 0; cc < 128; cc += 8) {
            float w[8];
            #pragma unroll
            for (int j = 0; j < 8; ++j)
                w[j] = opW[(cb + cc + j) * NN + n];   // 8 LDGs in flight
            #pragma unroll
            for (int r = 0; r < 4; ++r) {
                const float4 p0 = *(const float4*)&ps[r * CC + cb + cc];
                const float4 p1 = *(const float4*)&ps[r * CC + cb + cc + 4];
                acc[r] += p0.x * w[0] + p0.y * w[1] + p0.z * w[2] + p0.w * w[3]
                        + p1.x * w[4] + p1.y * w[5] + p1.z * w[6] + p1.w * w[7];
            }
        }

        #pragma unroll
        for (int r = 0; r < 4; ++r) red[q * 512 + r * NN + n] = acc[r];
        __syncthreads();
        if (q == 0) {
            const float bias = opb[n];
            #pragma unroll
            for (int r = 0; r < 4; ++r) {
                const float imp = red[r * NN + n] + red[512 + r * NN + n]
                                + red[1024 + r * NN + n] + red[1536 + r * NN + n]
                                + bias;
                const int idx = (b0 + r) * NN + n;
                const float m = mask[idx];
                out[idx] = x[idx] * (1.0f - m) + imp * m;
            }
        }
    }
}

// ---------------------------------------------------------------------------
extern "C" void kernel_launch(void* const* d_in, const int* in_sizes, int n_in,
                              void* d_out, int out_size) {
    (void)in_sizes; (void)out_size;
    const float* x    = (const float*)d_in[0];
    const float* mask = (const float*)d_in[1];
    const float* emb  = (const float*)d_in[2];
    const float* gatW = (const float*)d_in[3];
    const float* fpW  = (const float*)d_in[5];
    const float* fpb  = (const float*)d_in[6];
    const float* opW  = (const float*)d_in[7];
    const float* opb  = (const float*)d_in[8];
    const int*   kptr = (n_in >= 10) ? (const int*)d_in[9] : nullptr;

    float* out = (float*)d_out;
    float* adj = out + BW * NN;

    fused_kernel<<<GRID, TPB>>>(x, mask, emb, gatW, fpW, fpb, opW, opb,
                                kptr, out, adj);
}

// round 14
// speedup vs baseline: 4.2039x; 1.0140x over previous
#include <cuda_runtime.h>

// MissingValueImputer — algebraically reduced (R2): GAT output is exactly
// relu(h0 @ gat_W^T), independent of node index and adjacency.
// R13: no smem weight staging anywhere. Weights stream straight from L2 as
// LDG.128 with deep MLP; h0/p live in smem as float4-over-r so every reuse
// is a single broadcast LDS.128. 5 barriers total (was ~20).

#define BW 512
#define NN 128
#define FF 128
#define CC 512
#define TPB 512
#define GRID 128

// smem (floats):
//   pool [0,8192): ph1 xs4[512] + red1[4096]@512 + adj@4608; ph3 red3[8192]
//   h0s4 [8192,8704):  h0s4[f*4+r]
//   ps4  [8704,10752): ps4[c*4+r]
#define SM_H0S 8192
#define SM_PS  8704
#define SM_TOT 10752

__global__ __launch_bounds__(TPB, 1)
void fused_kernel(const float* __restrict__ x, const float* __restrict__ mask,
                  const float* __restrict__ emb, const float* __restrict__ gatW,
                  const float* __restrict__ fpW, const float* __restrict__ fpb,
                  const float* __restrict__ opW, const float* __restrict__ opb,
                  const int* __restrict__ kptr,
                  float* __restrict__ out, float* __restrict__ adj_out) {
    __shared__ __align__(16) float sm[SM_TOT];
    const int t = threadIdx.x;
    const int blk = blockIdx.x;
    const int b0 = blk * 4;
    float* h0s4 = sm + SM_H0S;
    float* ps4  = sm + SM_PS;

    // ============ Phase 1: h0 (t<256) + adjacency (256<=t<384) =============
    if (t < 256) {
        // h0[r][o] = fp_b[o] + sum_f x[r][f] * fpW[f][o], partials by f-group
        float* xs4  = sm;        // [128 f][4 r]
        float* red1 = sm + 512;  // [8 fq][4 r][32 o4][4]
        for (int i = t; i < 512; i += 256) {
            const int f = i & 127, r = i >> 7;
            xs4[f * 4 + r] = x[b0 * NN + i];
        }
        asm volatile("bar.sync 3, 256;" ::: "memory");

        const int o4 = t & 31, fq = t >> 5;
        const float4* fw4 = (const float4*)fpW;  // [f][o4]
        float4 a0 = {0,0,0,0}, a1 = {0,0,0,0}, a2 = {0,0,0,0}, a3 = {0,0,0,0};
        #pragma unroll 8
        for (int f = fq * 16; f < fq * 16 + 16; ++f) {
            const float4 wv = fw4[f * 32 + o4];              // LDG.128
            const float4 xv = *(const float4*)&xs4[f * 4];   // bcast LDS.128
            a0.x += xv.x * wv.x; a0.y += xv.x * wv.y; a0.z += xv.x * wv.z; a0.w += xv.x * wv.w;
            a1.x += xv.y * wv.x; a1.y += xv.y * wv.y; a1.z += xv.y * wv.z; a1.w += xv.y * wv.w;
            a2.x += xv.z * wv.x; a2.y += xv.z * wv.y; a2.z += xv.z * wv.z; a2.w += xv.z * wv.w;
            a3.x += xv.w * wv.x; a3.y += xv.w * wv.y; a3.z += xv.w * wv.z; a3.w += xv.w * wv.w;
        }
        float* rb = red1 + fq * 512 + o4 * 4;
        *(float4*)&rb[0]   = a0;
        *(float4*)&rb[128] = a1;
        *(float4*)&rb[256] = a2;
        *(float4*)&rb[384] = a3;
    } else if (t < 384) {
        // adjacency row i = blk
        const int t2 = t - 256;
        float* ei = sm + 4608;      // [128]
        float* simrow = sm + 4736;  // [128]
        ei[t2] = emb[blk * FF + t2];
        asm volatile("bar.sync 4, 128;" ::: "memory");

        const float4* rowv = (const float4*)(emb + t2 * FF);
        const float4* eiv  = (const float4*)ei;
        float nj = 0.f, dot = 0.f;
        #pragma unroll
        for (int f = 0; f < FF / 4; ++f) {
            float4 rr = rowv[f];
            float4 ee = eiv[f];
            nj  += rr.x * rr.x + rr.y * rr.y + rr.z * rr.z + rr.w * rr.w;
            dot += ee.x * rr.x + ee.y * rr.y + ee.z * rr.z + ee.w * rr.w;
        }
        const float invj = 1.0f / sqrtf(nj);
        if (t2 == blk) sm[4864] = invj;
        asm volatile("bar.sync 4, 128;" ::: "memory");
        simrow[t2] = dot * invj * sm[4864];
        asm volatile("bar.sync 4, 128;" ::: "memory");

        const int k = kptr ? *kptr : 30;
        const float mine = simrow[t2];
        int rank = 0;
        #pragma unroll 16
        for (int j = 0; j < NN; ++j) {
            const float v = simrow[j];
            rank += (v > mine || (v == mine && j < t2)) ? 1 : 0;
        }
        adj_out[blk * NN + t2] = (rank < k) ? 1.0f : 0.0f;
    }
    __syncthreads();

    // finalize h0s4[f*4+r] (t<128)
    if (t < 128) {
        const int r = t >> 5, o4 = t & 31;
        const float* red1 = sm + 512;
        float4 s = {0,0,0,0};
        #pragma unroll
        for (int fq = 0; fq < 8; ++fq) {
            const float4 v = *(const float4*)&red1[fq * 512 + r * 128 + o4 * 4];
            s.x += v.x; s.y += v.y; s.z += v.z; s.w += v.w;
        }
        const float4 bv = ((const float4*)fpb)[o4];
        s.x += bv.x; s.y += bv.y; s.z += bv.z; s.w += bv.w;
        h0s4[(o4 * 4 + 0) * 4 + r] = s.x;
        h0s4[(o4 * 4 + 1) * 4 + r] = s.y;
        h0s4[(o4 * 4 + 2) * 4 + r] = s.z;
        h0s4[(o4 * 4 + 3) * 4 + r] = s.w;
    }
    __syncthreads();

    // ============ Phase 2: ps4[c] = relu over r of gatW[c] . h0 ============
    // Thread owns full row c. No barriers, no staging; h0 reuse = bcast LDS.
    {
        const float4* gw4 = (const float4*)(gatW + t * FF);  // row c = t
        float4 a = {0,0,0,0};  // over r
        #pragma unroll 8
        for (int f4 = 0; f4 < 32; ++f4) {
            const float4 wv = gw4[f4];                               // LDG.128
            const float4 h0 = *(const float4*)&h0s4[(f4 * 4 + 0) * 4];
            const float4 h1 = *(const float4*)&h0s4[(f4 * 4 + 1) * 4];
            const float4 h2 = *(const float4*)&h0s4[(f4 * 4 + 2) * 4];
            const float4 h3 = *(const float4*)&h0s4[(f4 * 4 + 3) * 4];
            a.x += wv.x * h0.x + wv.y * h1.x + wv.z * h2.x + wv.w * h3.x;
            a.y += wv.x * h0.y + wv.y * h1.y + wv.z * h2.y + wv.w * h3.y;
            a.z += wv.x * h0.z + wv.y * h1.z + wv.z * h2.z + wv.w * h3.z;
            a.w += wv.x * h0.w + wv.y * h1.w + wv.z * h2.w + wv.w * h3.w;
        }
        a.x = fmaxf(a.x, 0.f); a.y = fmaxf(a.y, 0.f);
        a.z = fmaxf(a.z, 0.f); a.w = fmaxf(a.w, 0.f);
        *(float4*)&ps4[t * 4] = a;
    }
    __syncthreads();

    // ============ Phase 3: imp = p @ opW + opb; blend ======================
    // 16 c-quarters x 32 n4; opW float4 along n (coalesced), p bcast LDS.
    {
        const int cq = t >> 5, n4 = t & 31;
        const float4* ow4 = (const float4*)opW;  // [c][n4]
        float4 acc0 = {0,0,0,0}, acc1 = {0,0,0,0},
               acc2 = {0,0,0,0}, acc3 = {0,0,0,0};
        const int c0 = cq * 32;
        #pragma unroll 8
        for (int c = c0; c < c0 + 32; ++c) {
            const float4 wv = ow4[c * 32 + n4];             // LDG.128
            const float4 pv = *(const float4*)&ps4[c * 4];  // bcast LDS.128
            acc0.x += pv.x * wv.x; acc0.y += pv.x * wv.y; acc0.z += pv.x * wv.z; acc0.w += pv.x * wv.w;
            acc1.x += pv.y * wv.x; acc1.y += pv.y * wv.y; acc1.z += pv.y * wv.z; acc1.w += pv.y * wv.w;
            acc2.x += pv.z * wv.x; acc2.y += pv.z * wv.y; acc2.z += pv.z * wv.z; acc2.w += pv.z * wv.w;
            acc3.x += pv.w * wv.x; acc3.y += pv.w * wv.y; acc3.z += pv.w * wv.z; acc3.w += pv.w * wv.w;
        }
        float* red3 = sm;  // [16 cq][4 r][32 n4][4]
        float* rb = red3 + (cq * 4) * 128 + n4 * 4;
        *(float4*)&rb[0]   = acc0;
        *(float4*)&rb[128] = acc1;
        *(float4*)&rb[256] = acc2;
        *(float4*)&rb[384] = acc3;
    }
    __syncthreads();

    if (t < 128) {
        const int r = t >> 5, n4 = t & 31;
        const float* red3 = sm;
        float4 s = {0,0,0,0};
        #pragma unroll
        for (int cq = 0; cq < 16; ++cq) {
            const float4 v = *(const float4*)&red3[cq * 512 + r * 128 + n4 * 4];
            s.x += v.x; s.y += v.y; s.z += v.z; s.w += v.w;
        }
        const float4 bv = ((const float4*)opb)[n4];
        s.x += bv.x; s.y += bv.y; s.z += bv.z; s.w += bv.w;

        const int i4 = ((b0 + r) * NN) / 4 + n4;
        const float4 xv = ((const float4*)x)[i4];
        const float4 mv = ((const float4*)mask)[i4];
        float4 o;
        o.x = xv.x * (1.0f - mv.x) + s.x * mv.x;
        o.y = xv.y * (1.0f - mv.y) + s.y * mv.y;
        o.z = xv.z * (1.0f - mv.z) + s.z * mv.z;
        o.w = xv.w * (1.0f - mv.w) + s.w * mv.w;
        ((float4*)out)[i4] = o;
    }
}

// ---------------------------------------------------------------------------
extern "C" void kernel_launch(void* const* d_in, const int* in_sizes, int n_in,
                              void* d_out, int out_size) {
    (void)in_sizes; (void)out_size;
    const float* x    = (const float*)d_in[0];
    const float* mask = (const float*)d_in[1];
    const float* emb  = (const float*)d_in[2];
    const float* gatW = (const float*)d_in[3];
    const float* fpW  = (const float*)d_in[5];
    const float* fpb  = (const float*)d_in[6];
    const float* opW  = (const float*)d_in[7];
    const float* opb  = (const float*)d_in[8];
    const int*   kptr = (n_in >= 10) ? (const int*)d_in[9] : nullptr;

    float* out = (float*)d_out;
    float* adj = out + BW * NN;

    fused_kernel<<<GRID, TPB>>>(x, mask, emb, gatW, fpW, fpb, opW, opb,
                                kptr, out, adj);
}